// round 1
// baseline (speedup 1.0000x reference)
#include <cuda_runtime.h>
#include <math.h>
#include <float.h>

#define NMAX 20000
#define EMAX 320000
#define H 128
#define T 4
#define FIN 32
#define FULLM 0xffffffffu

// ---------------- device scratch (no allocations allowed) ----------------
__device__ float g_avg_log;
__device__ float g_enc[5 * FIN];              // bond_emb @ enc_w + enc_b, per bond type
__device__ int   g_deg[NMAX];
__device__ int   g_off[NMAX + 1];
__device__ int   g_fill[NMAX];
__device__ int   g_csr[EMAX];
__device__ float g_agg[(size_t)NMAX * T * 5 * FIN];   // [n][t][{sum,mean,min,max,std}][32]
__device__ float g_y[(size_t)NMAX * H];               // post-MLP output

// ---------------- scalars: avg_log + bond encode table ----------------
__global__ void k_scalars(const int* __restrict__ mol_deg,
                          const float* __restrict__ bond_emb,
                          const float* __restrict__ enc_w,
                          const float* __restrict__ enc_b) {
    __shared__ float s_num[256], s_den[256];
    int tid = threadIdx.x;
    float num = 0.f, den = 0.f;
    if (tid < 128) {
        float d = (float)mol_deg[tid];
        num = logf((float)tid + 1.0f) * d;
        den = d;
    }
    s_num[tid] = num; s_den[tid] = den;
    __syncthreads();
    for (int off = 128; off > 0; off >>= 1) {
        if (tid < off) { s_num[tid] += s_num[tid + off]; s_den[tid] += s_den[tid + off]; }
        __syncthreads();
    }
    if (tid == 0) g_avg_log = s_num[0] / s_den[0];

    if (tid < 5 * FIN) {
        int b = tid >> 5, g = tid & 31;
        float a = enc_b[g];
        for (int k = 0; k < H; k++) a += bond_emb[b * H + k] * enc_w[k * FIN + g];
        g_enc[b * FIN + g] = a;
    }
}

__global__ void k_zero(int n) {
    int i = blockIdx.x * blockDim.x + threadIdx.x;
    if (i < n) g_deg[i] = 0;
}

__global__ void k_hist(const int* __restrict__ dst, int E) {
    int e = blockIdx.x * blockDim.x + threadIdx.x;
    if (e < E) atomicAdd(&g_deg[dst[e]], 1);
}

// single-block exclusive scan over g_deg -> g_off, g_fill
__global__ void k_scan(int n) {
    __shared__ int sh[1024];
    __shared__ int carry;
    int tid = threadIdx.x;
    if (tid == 0) carry = 0;
    __syncthreads();
    for (int base = 0; base < n; base += 1024) {
        int i = base + tid;
        int v = (i < n) ? g_deg[i] : 0;
        sh[tid] = v;
        __syncthreads();
        for (int off = 1; off < 1024; off <<= 1) {
            int tv = (tid >= off) ? sh[tid - off] : 0;
            __syncthreads();
            sh[tid] += tv;
            __syncthreads();
        }
        int excl = sh[tid] - v;
        if (i < n) { g_off[i] = carry + excl; g_fill[i] = carry + excl; }
        __syncthreads();
        if (tid == 0) carry += sh[1023];
        __syncthreads();
    }
    if (tid == 0) g_off[n] = carry;
}

__global__ void k_scatter(const int* __restrict__ dst, int E) {
    int e = blockIdx.x * blockDim.x + threadIdx.x;
    if (e < E) {
        int p = atomicAdd(&g_fill[dst[e]], 1);
        g_csr[p] = e;
    }
}

// ---------------- per-node edge pre-MLP + multi-aggregation ----------------
// block = 128 threads = 4 warps, warp t handles tower t, lane = output feature.
// Persistent over nodes; weights live in registers.
__global__ void __launch_bounds__(128) k_agg(
    const float* __restrict__ atom_x, const int* __restrict__ bond,
    const int* __restrict__ src,
    const float* __restrict__ pre_w1, const float* __restrict__ pre_b1,
    const float* __restrict__ pre_w2, const float* __restrict__ pre_b2,
    int N) {
    const int l = threadIdx.x & 31;
    const int t = threadIdx.x >> 5;

    float w1a[FIN], w1b[FIN], w2[FIN];
#pragma unroll
    for (int f = 0; f < FIN; f++) w1a[f] = pre_w1[(t * 96 + f) * FIN + l];
#pragma unroll
    for (int f = 0; f < FIN; f++) w1b[f] = pre_w1[(t * 96 + 32 + f) * FIN + l];
#pragma unroll
    for (int f = 0; f < FIN; f++) w2[f] = pre_w2[(t * FIN + f) * FIN + l];
    float b1 = pre_b1[t * FIN + l];
    float b2 = pre_b2[t * FIN + l];

    // ea contribution to layer-1: only 5 distinct bond types
    float evc0, evc1, evc2, evc3, evc4;
    {
        float ev[5];
#pragma unroll
        for (int b = 0; b < 5; b++) {
            float et = g_enc[b * FIN + l];
            float a = 0.f;
#pragma unroll
            for (int f = 0; f < FIN; f++)
                a += __shfl_sync(FULLM, et, f) * pre_w1[(t * 96 + 64 + f) * FIN + l];
            ev[b] = a;
        }
        evc0 = ev[0]; evc1 = ev[1]; evc2 = ev[2]; evc3 = ev[3]; evc4 = ev[4];
    }

    for (int n = blockIdx.x; n < N; n += gridDim.x) {
        float xd = atom_x[n * H + t * FIN + l];
        float a0 = b1;  // x[dst] contribution: constant across this node's edges
#pragma unroll
        for (int f = 0; f < FIN; f++) a0 += __shfl_sync(FULLM, xd, f) * w1a[f];

        int e0 = g_off[n], e1 = g_off[n + 1];
        float s_sum = 0.f, s_sq = 0.f, s_min = FLT_MAX, s_max = -FLT_MAX;

        float xs_nxt = 0.f; int b_nxt = 0;
        if (e0 < e1) {
            int e = g_csr[e0];
            xs_nxt = atom_x[src[e] * H + t * FIN + l];
            b_nxt = bond[e];
        }
        for (int i = e0; i < e1; i++) {
            float xs = xs_nxt; int bb = b_nxt;
            if (i + 1 < e1) {
                int e = g_csr[i + 1];
                xs_nxt = atom_x[src[e] * H + t * FIN + l];
                b_nxt = bond[e];
            }
            float ev = evc0;
            ev = (bb == 1) ? evc1 : ev;
            ev = (bb == 2) ? evc2 : ev;
            ev = (bb == 3) ? evc3 : ev;
            ev = (bb == 4) ? evc4 : ev;
            float a = a0 + ev;
#pragma unroll
            for (int f = 0; f < FIN; f++) a += __shfl_sync(FULLM, xs, f) * w1b[f];
            float m1 = fmaxf(a, 0.f);
            float m = b2;
#pragma unroll
            for (int f = 0; f < FIN; f++) m += __shfl_sync(FULLM, m1, f) * w2[f];
            s_sum += m;
            s_sq += m * m;
            s_min = fminf(s_min, m);
            s_max = fmaxf(s_max, m);
        }
        int cnt = e1 - e0;
        float c1 = fmaxf((float)cnt, 1.f);
        float mean = s_sum / c1;
        float mean2 = s_sq / c1;
        float stdv = sqrtf(fmaxf(mean2 - mean * mean, 0.f) + 1e-5f);
        if (cnt == 0) { s_min = 0.f; s_max = 0.f; }
        float* o = g_agg + (size_t)(n * T + t) * 5 * FIN + l;
        o[0 * FIN] = s_sum;
        o[1 * FIN] = mean;
        o[2 * FIN] = s_min;
        o[3 * FIN] = s_max;
        o[4 * FIN] = stdv;
    }
}

// ---------------- post-MLP per tower ----------------
// grid (ceil(N/64), T); block 128 = 4 warps; each warp: 16 nodes in 4-node groups.
__global__ void __launch_bounds__(128) k_post(
    const float* __restrict__ atom_x,
    const float* __restrict__ post_w1, const float* __restrict__ post_b1,
    const float* __restrict__ post_w2, const float* __restrict__ post_b2,
    int N) {
    const int t = blockIdx.y;
    const int w = threadIdx.x >> 5;
    const int g = threadIdx.x & 31;
    __shared__ float st[4][4][512];  // [warp][node][feature]

    const float avg = g_avg_log;
    const float* w1 = post_w1 + (size_t)t * 512 * FIN;
    const float b1 = post_b1[t * FIN + g];
    const float b2v = post_b2[t * FIN + g];
    const int base = blockIdx.x * 64 + w * 16;

    for (int grp = 0; grp < 4; grp++) {
        int n0 = base + grp * 4;
#pragma unroll
        for (int j = 0; j < 4; j++) {
            int n = min(n0 + j, N - 1);
            int cnt = g_deg[n];
            float c1 = fmaxf((float)cnt, 1.f);
            float logd = logf(c1 + 1.f);
            float s1 = logd / avg, s2 = avg / logd;
            st[w][j][g] = atom_x[n * H + t * FIN + g];
            const float* ag = g_agg + (size_t)(n * T + t) * 5 * FIN;
#pragma unroll
            for (int a = 0; a < 5; a++) {
                float v = ag[a * FIN + g];
                st[w][j][32 + a * FIN + g] = v;
                st[w][j][192 + a * FIN + g] = v * s1;
                st[w][j][352 + a * FIN + g] = v * s2;
            }
        }
        __syncwarp();
        float acc0 = b1, acc1 = b1, acc2 = b1, acc3 = b1;
#pragma unroll 8
        for (int f = 0; f < 512; f++) {
            float wv = w1[f * FIN + g];
            acc0 += st[w][0][f] * wv;
            acc1 += st[w][1][f] * wv;
            acc2 += st[w][2][f] * wv;
            acc3 += st[w][3][f] * wv;
        }
        float m0 = fmaxf(acc0, 0.f), m1 = fmaxf(acc1, 0.f);
        float m2 = fmaxf(acc2, 0.f), m3 = fmaxf(acc3, 0.f);
        float o0 = b2v, o1 = b2v, o2 = b2v, o3 = b2v;
#pragma unroll
        for (int f = 0; f < FIN; f++) {
            float wv = post_w2[(t * FIN + f) * FIN + g];
            o0 += __shfl_sync(FULLM, m0, f) * wv;
            o1 += __shfl_sync(FULLM, m1, f) * wv;
            o2 += __shfl_sync(FULLM, m2, f) * wv;
            o3 += __shfl_sync(FULLM, m3, f) * wv;
        }
        if (n0 + 0 < N) g_y[(n0 + 0) * H + t * FIN + g] = o0;
        if (n0 + 1 < N) g_y[(n0 + 1) * H + t * FIN + g] = o1;
        if (n0 + 2 < N) g_y[(n0 + 2) * H + t * FIN + g] = o2;
        if (n0 + 3 < N) g_y[(n0 + 3) * H + t * FIN + g] = o3;
        __syncwarp();
    }
}

// ---------------- final linear + LayerNorm + ReLU residual ----------------
// block 128 threads = one node's 128 output features; 16 nodes per block (4x4).
__global__ void __launch_bounds__(128) k_final(
    const float* __restrict__ atom_x,
    const float* __restrict__ lin_w, const float* __restrict__ lin_b,
    const float* __restrict__ ln_g, const float* __restrict__ ln_b,
    float* __restrict__ out, int N) {
    const int o = threadIdx.x;
    const int wid = o >> 5, l = o & 31;
    __shared__ float sy[4][H];
    __shared__ float red_s[4][4], red_q[4][4];
    const float lb = lin_b[o], gamma = ln_g[o], beta = ln_b[o];

    for (int grp = 0; grp < 4; grp++) {
        int n0 = blockIdx.x * 16 + grp * 4;
        __syncthreads();
#pragma unroll
        for (int j = 0; j < 4; j++) {
            int n = min(n0 + j, N - 1);
            sy[j][o] = g_y[n * H + o];
        }
        __syncthreads();
        float a0 = lb, a1 = lb, a2 = lb, a3 = lb;
#pragma unroll 8
        for (int k = 0; k < H; k++) {
            float wv = lin_w[k * H + o];
            a0 += sy[0][k] * wv;
            a1 += sy[1][k] * wv;
            a2 += sy[2][k] * wv;
            a3 += sy[3][k] * wv;
        }
        float acc[4] = {a0, a1, a2, a3};
#pragma unroll
        for (int j = 0; j < 4; j++) {
            float s = acc[j], q = acc[j] * acc[j];
#pragma unroll
            for (int off = 16; off > 0; off >>= 1) {
                s += __shfl_xor_sync(FULLM, s, off);
                q += __shfl_xor_sync(FULLM, q, off);
            }
            if (l == 0) { red_s[j][wid] = s; red_q[j][wid] = q; }
        }
        __syncthreads();
#pragma unroll
        for (int j = 0; j < 4; j++) {
            int n = n0 + j;
            if (n >= N) continue;
            float s = red_s[j][0] + red_s[j][1] + red_s[j][2] + red_s[j][3];
            float q = red_q[j][0] + red_q[j][1] + red_q[j][2] + red_q[j][3];
            float mu = s * (1.f / 128.f);
            float var = q * (1.f / 128.f) - mu * mu;
            float v = (acc[j] - mu) * rsqrtf(var + 1e-5f) * gamma + beta;
            out[n * H + o] = atom_x[n * H + o] + fmaxf(v, 0.f);
        }
    }
}

// ---------------- launch ----------------
extern "C" void kernel_launch(void* const* d_in, const int* in_sizes, int n_in,
                              void* d_out, int out_size) {
    const float* atom_x  = (const float*)d_in[0];
    const int*   bond_x  = (const int*)d_in[1];
    const int*   edge_ix = (const int*)d_in[2];
    const int*   mol_deg = (const int*)d_in[3];
    const float* bond_emb = (const float*)d_in[4];
    const float* enc_w   = (const float*)d_in[5];
    const float* enc_b   = (const float*)d_in[6];
    const float* pre_w1  = (const float*)d_in[7];
    const float* pre_b1  = (const float*)d_in[8];
    const float* pre_w2  = (const float*)d_in[9];
    const float* pre_b2  = (const float*)d_in[10];
    const float* post_w1 = (const float*)d_in[11];
    const float* post_b1 = (const float*)d_in[12];
    const float* post_w2 = (const float*)d_in[13];
    const float* post_b2 = (const float*)d_in[14];
    const float* lin_w   = (const float*)d_in[15];
    const float* lin_b   = (const float*)d_in[16];
    const float* ln_g    = (const float*)d_in[17];
    const float* ln_b    = (const float*)d_in[18];
    float* out = (float*)d_out;

    int N = in_sizes[0] / H;
    int E = in_sizes[1];
    const int* src = edge_ix;
    const int* dst = edge_ix + E;

    k_zero<<<(N + 511) / 512, 512>>>(N);
    k_scalars<<<1, 256>>>(mol_deg, bond_emb, enc_w, enc_b);
    k_hist<<<(E + 255) / 256, 256>>>(dst, E);
    k_scan<<<1, 1024>>>(N);
    k_scatter<<<(E + 255) / 256, 256>>>(dst, E);
    k_agg<<<888, 128>>>(atom_x, bond_x, src, pre_w1, pre_b1, pre_w2, pre_b2, N);
    k_post<<<dim3((N + 63) / 64, T), 128>>>(atom_x, post_w1, post_b1, post_w2, post_b2, N);
    k_final<<<(N + 15) / 16, 128>>>(atom_x, lin_w, lin_b, ln_g, ln_b, out, N);
}

// round 2
// speedup vs baseline: 2.0824x; 2.0824x over previous
#include <cuda_runtime.h>
#include <math.h>
#include <float.h>

#define NMAX 20000
#define EMAX 320000
#define H 128
#define T 4
#define FIN 32
#define FULLM 0xffffffffu

// ---------------- device scratch ----------------
__device__ float g_avg_log;
__device__ float g_enc[5 * FIN];
__device__ int   g_deg[NMAX];
__device__ int   g_off[NMAX + 1];
__device__ int   g_fill[NMAX];
__device__ int   g_csr[EMAX];                 // packed: src | (bond<<27)
__device__ int   g_part[64];
__device__ int   g_poff[64];
__device__ float g_a0[(size_t)NMAX * H];      // b1 + W1a·x[n], per tower/lane
__device__ float g_p [(size_t)NMAX * H];      // W1b·x[n]
__device__ float g_agg[(size_t)NMAX * T * 5 * FIN];
__device__ float g_y[(size_t)NMAX * H];

// ---------------- scalars ----------------
__global__ void k_scalars(const int* __restrict__ mol_deg,
                          const float* __restrict__ bond_emb,
                          const float* __restrict__ enc_w,
                          const float* __restrict__ enc_b) {
    __shared__ float s_num[256], s_den[256];
    int tid = threadIdx.x;
    float num = 0.f, den = 0.f;
    if (tid < 128) {
        float d = (float)mol_deg[tid];
        num = logf((float)tid + 1.0f) * d;
        den = d;
    }
    s_num[tid] = num; s_den[tid] = den;
    __syncthreads();
    for (int off = 128; off > 0; off >>= 1) {
        if (tid < off) { s_num[tid] += s_num[tid + off]; s_den[tid] += s_den[tid + off]; }
        __syncthreads();
    }
    if (tid == 0) g_avg_log = s_num[0] / s_den[0];

    if (tid < 5 * FIN) {
        int b = tid >> 5, g = tid & 31;
        float a = enc_b[g];
        for (int k = 0; k < H; k++) a += bond_emb[b * H + k] * enc_w[k * FIN + g];
        g_enc[b * FIN + g] = a;
    }
}

__global__ void k_zero(int n) {
    int i = blockIdx.x * blockDim.x + threadIdx.x;
    if (i < n) g_deg[i] = 0;
}

__global__ void k_hist(const int* __restrict__ dst, int E) {
    int e = blockIdx.x * blockDim.x + threadIdx.x;
    if (e < E) atomicAdd(&g_deg[dst[e]], 1);
}

// ---------------- parallel 3-phase scan ----------------
__global__ void k_scan1(int n) {
    __shared__ int sh[1024];
    int tid = threadIdx.x;
    int i = blockIdx.x * 1024 + tid;
    int v = (i < n) ? g_deg[i] : 0;
    sh[tid] = v;
    __syncthreads();
    for (int off = 1; off < 1024; off <<= 1) {
        int tv = (tid >= off) ? sh[tid - off] : 0;
        __syncthreads();
        sh[tid] += tv;
        __syncthreads();
    }
    if (i < n) g_off[i] = sh[tid] - v;       // local exclusive
    if (tid == 1023) g_part[blockIdx.x] = sh[1023];
}

__global__ void k_scan2(int nb, int n, int E) {
    int l = threadIdx.x;
    int v = (l < nb) ? g_part[l] : 0;
    int s = v;
#pragma unroll
    for (int off = 1; off < 32; off <<= 1) {
        int t = __shfl_up_sync(FULLM, s, off);
        if (l >= off) s += t;
    }
    g_poff[l] = s - v;                        // exclusive block offsets
    if (l == 0) g_off[n] = E;
}

__global__ void k_scan3(int n) {
    int i = blockIdx.x * 1024 + threadIdx.x;
    if (i < n) {
        int v = g_off[i] + g_poff[blockIdx.x];
        g_off[i] = v;
        g_fill[i] = v;
    }
}

__global__ void k_scatter(const int* __restrict__ dst, const int* __restrict__ src,
                          const int* __restrict__ bond, int E) {
    int e = blockIdx.x * blockDim.x + threadIdx.x;
    if (e < E) {
        int p = atomicAdd(&g_fill[dst[e]], 1);
        g_csr[p] = src[e] | (bond[e] << 27);
    }
}

// ---------------- per-node precompute: A0 = b1 + W1a.x, P = W1b.x ----------------
__global__ void __launch_bounds__(128) k_pre(
    const float* __restrict__ atom_x,
    const float* __restrict__ pre_w1, const float* __restrict__ pre_b1, int N) {
    const int l = threadIdx.x & 31;
    const int t = threadIdx.x >> 5;
    float w1a[FIN], w1b[FIN];
#pragma unroll
    for (int f = 0; f < FIN; f++) w1a[f] = pre_w1[(t * 96 + f) * FIN + l];
#pragma unroll
    for (int f = 0; f < FIN; f++) w1b[f] = pre_w1[(t * 96 + 32 + f) * FIN + l];
    const float b1 = pre_b1[t * FIN + l];

    for (int n = blockIdx.x; n < N; n += gridDim.x) {
        float x = atom_x[n * H + t * FIN + l];
        float a0 = b1, p = 0.f;
#pragma unroll
        for (int f = 0; f < FIN; f++) {
            float xf = __shfl_sync(FULLM, x, f);
            a0 += xf * w1a[f];
            p  += xf * w1b[f];
        }
        g_a0[n * H + t * FIN + l] = a0;
        g_p [n * H + t * FIN + l] = p;
    }
}

// ---------------- edge loop: layer2 + multi-aggregation ----------------
__global__ void __launch_bounds__(128) k_agg(
    const float* __restrict__ pre_w1,
    const float* __restrict__ pre_w2, const float* __restrict__ pre_b2, int N) {
    const int l = threadIdx.x & 31;
    const int t = threadIdx.x >> 5;

    float w2[FIN];
#pragma unroll
    for (int f = 0; f < FIN; f++) w2[f] = pre_w2[(t * FIN + f) * FIN + l];
    const float b2 = pre_b2[t * FIN + l];

    float evc0, evc1, evc2, evc3, evc4;
    {
        float w1c[FIN];
#pragma unroll
        for (int f = 0; f < FIN; f++) w1c[f] = pre_w1[(t * 96 + 64 + f) * FIN + l];
        float ev[5];
#pragma unroll
        for (int b = 0; b < 5; b++) {
            float et = g_enc[b * FIN + l];
            float a = 0.f;
#pragma unroll
            for (int f = 0; f < FIN; f++) a += __shfl_sync(FULLM, et, f) * w1c[f];
            ev[b] = a;
        }
        evc0 = ev[0]; evc1 = ev[1]; evc2 = ev[2]; evc3 = ev[3]; evc4 = ev[4];
    }

    for (int n = blockIdx.x; n < N; n += gridDim.x) {
        float a0 = g_a0[n * H + t * FIN + l];
        int e0 = g_off[n], e1 = g_off[n + 1];
        float s_sum = 0.f, s_sq = 0.f, s_min = FLT_MAX, s_max = -FLT_MAX;

        float p_nxt = 0.f; int b_nxt = 0;
        if (e0 < e1) {
            int pk = g_csr[e0];
            p_nxt = g_p[(pk & 0x07ffffff) * H + t * FIN + l];
            b_nxt = pk >> 27;
        }
        for (int i = e0; i < e1; i++) {
            float p = p_nxt; int bb = b_nxt;
            if (i + 1 < e1) {
                int pk = g_csr[i + 1];
                p_nxt = g_p[(pk & 0x07ffffff) * H + t * FIN + l];
                b_nxt = pk >> 27;
            }
            float ev = evc0;
            ev = (bb == 1) ? evc1 : ev;
            ev = (bb == 2) ? evc2 : ev;
            ev = (bb == 3) ? evc3 : ev;
            ev = (bb == 4) ? evc4 : ev;
            float r = fmaxf(a0 + ev + p, 0.f);
            float m = b2;
#pragma unroll
            for (int f = 0; f < FIN; f++) m += __shfl_sync(FULLM, r, f) * w2[f];
            s_sum += m;
            s_sq += m * m;
            s_min = fminf(s_min, m);
            s_max = fmaxf(s_max, m);
        }
        int cnt = e1 - e0;
        float c1 = fmaxf((float)cnt, 1.f);
        float mean = s_sum / c1;
        float mean2 = s_sq / c1;
        float stdv = sqrtf(fmaxf(mean2 - mean * mean, 0.f) + 1e-5f);
        if (cnt == 0) { s_min = 0.f; s_max = 0.f; }
        float* o = g_agg + (size_t)(n * T + t) * 5 * FIN + l;
        o[0 * FIN] = s_sum;
        o[1 * FIN] = mean;
        o[2 * FIN] = s_min;
        o[3 * FIN] = s_max;
        o[4 * FIN] = stdv;
    }
}

// ---------------- post-MLP per tower ----------------
__global__ void __launch_bounds__(128) k_post(
    const float* __restrict__ atom_x,
    const float* __restrict__ post_w1, const float* __restrict__ post_b1,
    const float* __restrict__ post_w2, const float* __restrict__ post_b2,
    int N) {
    const int t = blockIdx.y;
    const int w = threadIdx.x >> 5;
    const int g = threadIdx.x & 31;
    __shared__ __align__(16) float st[4][4][512];

    const float avg = g_avg_log;
    const float* w1 = post_w1 + (size_t)t * 512 * FIN;
    const float b1 = post_b1[t * FIN + g];
    const float b2v = post_b2[t * FIN + g];
    const int base = blockIdx.x * 64 + w * 16;

    for (int grp = 0; grp < 4; grp++) {
        int n0 = base + grp * 4;
#pragma unroll
        for (int j = 0; j < 4; j++) {
            int n = min(n0 + j, N - 1);
            int cnt = g_deg[n];
            float c1 = fmaxf((float)cnt, 1.f);
            float logd = logf(c1 + 1.f);
            float s1 = logd / avg, s2 = avg / logd;
            st[w][j][g] = atom_x[n * H + t * FIN + g];
            const float* ag = g_agg + (size_t)(n * T + t) * 5 * FIN;
#pragma unroll
            for (int a = 0; a < 5; a++) {
                float v = ag[a * FIN + g];
                st[w][j][32 + a * FIN + g] = v;
                st[w][j][192 + a * FIN + g] = v * s1;
                st[w][j][352 + a * FIN + g] = v * s2;
            }
        }
        __syncwarp();
        const float4* s0 = (const float4*)st[w][0];
        const float4* s1v = (const float4*)st[w][1];
        const float4* s2v = (const float4*)st[w][2];
        const float4* s3v = (const float4*)st[w][3];
        float acc0 = b1, acc1 = b1, acc2 = b1, acc3 = b1;
#pragma unroll 4
        for (int ff = 0; ff < 128; ff++) {
            float4 v0 = s0[ff], v1 = s1v[ff], v2 = s2v[ff], v3 = s3v[ff];
#pragma unroll
            for (int c = 0; c < 4; c++) {
                float wv = w1[(4 * ff + c) * FIN + g];
                acc0 += ((const float*)&v0)[c] * wv;
                acc1 += ((const float*)&v1)[c] * wv;
                acc2 += ((const float*)&v2)[c] * wv;
                acc3 += ((const float*)&v3)[c] * wv;
            }
        }
        float m0 = fmaxf(acc0, 0.f), m1 = fmaxf(acc1, 0.f);
        float m2 = fmaxf(acc2, 0.f), m3 = fmaxf(acc3, 0.f);
        float o0 = b2v, o1 = b2v, o2 = b2v, o3 = b2v;
#pragma unroll
        for (int f = 0; f < FIN; f++) {
            float wv = post_w2[(t * FIN + f) * FIN + g];
            o0 += __shfl_sync(FULLM, m0, f) * wv;
            o1 += __shfl_sync(FULLM, m1, f) * wv;
            o2 += __shfl_sync(FULLM, m2, f) * wv;
            o3 += __shfl_sync(FULLM, m3, f) * wv;
        }
        if (n0 + 0 < N) g_y[(n0 + 0) * H + t * FIN + g] = o0;
        if (n0 + 1 < N) g_y[(n0 + 1) * H + t * FIN + g] = o1;
        if (n0 + 2 < N) g_y[(n0 + 2) * H + t * FIN + g] = o2;
        if (n0 + 3 < N) g_y[(n0 + 3) * H + t * FIN + g] = o3;
        __syncwarp();
    }
}

// ---------------- final linear + LayerNorm + ReLU residual ----------------
__global__ void __launch_bounds__(128) k_final(
    const float* __restrict__ atom_x,
    const float* __restrict__ lin_w, const float* __restrict__ lin_b,
    const float* __restrict__ ln_g, const float* __restrict__ ln_b,
    float* __restrict__ out, int N) {
    const int o = threadIdx.x;
    const int wid = o >> 5, l = o & 31;
    __shared__ __align__(16) float sy[4][H];
    __shared__ float red_s[4][4], red_q[4][4];
    const float lb = lin_b[o], gamma = ln_g[o], beta = ln_b[o];

    for (int grp = 0; grp < 4; grp++) {
        int n0 = blockIdx.x * 16 + grp * 4;
        __syncthreads();
#pragma unroll
        for (int j = 0; j < 4; j++) {
            int n = min(n0 + j, N - 1);
            sy[j][o] = g_y[n * H + o];
        }
        __syncthreads();
        const float4* y0 = (const float4*)sy[0];
        const float4* y1 = (const float4*)sy[1];
        const float4* y2 = (const float4*)sy[2];
        const float4* y3 = (const float4*)sy[3];
        float a0 = lb, a1 = lb, a2 = lb, a3 = lb;
#pragma unroll 4
        for (int kk = 0; kk < 32; kk++) {
            float4 v0 = y0[kk], v1 = y1[kk], v2 = y2[kk], v3 = y3[kk];
#pragma unroll
            for (int c = 0; c < 4; c++) {
                float wv = lin_w[(4 * kk + c) * H + o];
                a0 += ((const float*)&v0)[c] * wv;
                a1 += ((const float*)&v1)[c] * wv;
                a2 += ((const float*)&v2)[c] * wv;
                a3 += ((const float*)&v3)[c] * wv;
            }
        }
        float acc[4] = {a0, a1, a2, a3};
#pragma unroll
        for (int j = 0; j < 4; j++) {
            float s = acc[j], q = acc[j] * acc[j];
#pragma unroll
            for (int off = 16; off > 0; off >>= 1) {
                s += __shfl_xor_sync(FULLM, s, off);
                q += __shfl_xor_sync(FULLM, q, off);
            }
            if (l == 0) { red_s[j][wid] = s; red_q[j][wid] = q; }
        }
        __syncthreads();
#pragma unroll
        for (int j = 0; j < 4; j++) {
            int n = n0 + j;
            if (n >= N) continue;
            float s = red_s[j][0] + red_s[j][1] + red_s[j][2] + red_s[j][3];
            float q = red_q[j][0] + red_q[j][1] + red_q[j][2] + red_q[j][3];
            float mu = s * (1.f / 128.f);
            float var = q * (1.f / 128.f) - mu * mu;
            float v = (acc[j] - mu) * rsqrtf(var + 1e-5f) * gamma + beta;
            out[n * H + o] = atom_x[n * H + o] + fmaxf(v, 0.f);
        }
    }
}

// ---------------- launch ----------------
extern "C" void kernel_launch(void* const* d_in, const int* in_sizes, int n_in,
                              void* d_out, int out_size) {
    const float* atom_x  = (const float*)d_in[0];
    const int*   bond_x  = (const int*)d_in[1];
    const int*   edge_ix = (const int*)d_in[2];
    const int*   mol_deg = (const int*)d_in[3];
    const float* bond_emb = (const float*)d_in[4];
    const float* enc_w   = (const float*)d_in[5];
    const float* enc_b   = (const float*)d_in[6];
    const float* pre_w1  = (const float*)d_in[7];
    const float* pre_b1  = (const float*)d_in[8];
    const float* pre_w2  = (const float*)d_in[9];
    const float* pre_b2  = (const float*)d_in[10];
    const float* post_w1 = (const float*)d_in[11];
    const float* post_b1 = (const float*)d_in[12];
    const float* post_w2 = (const float*)d_in[13];
    const float* post_b2 = (const float*)d_in[14];
    const float* lin_w   = (const float*)d_in[15];
    const float* lin_b   = (const float*)d_in[16];
    const float* ln_g    = (const float*)d_in[17];
    const float* ln_b    = (const float*)d_in[18];
    float* out = (float*)d_out;

    int N = in_sizes[0] / H;
    int E = in_sizes[1];
    const int* src = edge_ix;
    const int* dst = edge_ix + E;
    int nb = (N + 1023) / 1024;

    k_zero<<<(N + 511) / 512, 512>>>(N);
    k_scalars<<<1, 256>>>(mol_deg, bond_emb, enc_w, enc_b);
    k_hist<<<(E + 255) / 256, 256>>>(dst, E);
    k_scan1<<<nb, 1024>>>(N);
    k_scan2<<<1, 32>>>(nb, N, E);
    k_scan3<<<nb, 1024>>>(N);
    k_scatter<<<(E + 255) / 256, 256>>>(dst, src, bond_x, E);
    k_pre<<<592, 128>>>(atom_x, pre_w1, pre_b1, N);
    k_agg<<<1184, 128>>>(pre_w1, pre_w2, pre_b2, N);
    k_post<<<dim3((N + 63) / 64, T), 128>>>(atom_x, post_w1, post_b1, post_w2, post_b2, N);
    k_final<<<(N + 15) / 16, 128>>>(atom_x, lin_w, lin_b, ln_g, ln_b, out, N);
}

// round 3
// speedup vs baseline: 2.0931x; 1.0051x over previous
#include <cuda_runtime.h>
#include <math.h>
#include <float.h>

#define NMAX 20000
#define EMAX 320000
#define H 128
#define T 4
#define FIN 32
#define FULLM 0xffffffffu

// ---------------- f32x2 packed helpers ----------------
__device__ __forceinline__ unsigned long long packf2(float lo, float hi) {
    unsigned long long r;
    asm("mov.b64 %0, {%1, %2};" : "=l"(r) : "r"(__float_as_uint(lo)), "r"(__float_as_uint(hi)));
    return r;
}
__device__ __forceinline__ void unpackf2(unsigned long long v, float& lo, float& hi) {
    unsigned int a, b;
    asm("mov.b64 {%0, %1}, %2;" : "=r"(a), "=r"(b) : "l"(v));
    lo = __uint_as_float(a); hi = __uint_as_float(b);
}
__device__ __forceinline__ unsigned long long fma2(unsigned long long a, unsigned long long b, unsigned long long c) {
    unsigned long long d;
    asm("fma.rn.f32x2 %0, %1, %2, %3;" : "=l"(d) : "l"(a), "l"(b), "l"(c));
    return d;
}
__device__ __forceinline__ unsigned long long add2(unsigned long long a, unsigned long long b) {
    unsigned long long d;
    asm("add.rn.f32x2 %0, %1, %2;" : "=l"(d) : "l"(a), "l"(b));
    return d;
}

// ---------------- device scratch ----------------
__device__ float g_avg_log;
__device__ float g_enc[5 * FIN];
__device__ int   g_deg[NMAX];
__device__ int   g_off[NMAX + 1];
__device__ int   g_fill[NMAX];
__device__ int   g_csr[EMAX];                 // packed: src | (bond<<27)
__device__ int   g_part[64];
__device__ int   g_poff[64];
__device__ float g_a0[(size_t)NMAX * H];      // b1 + W1a.x[n]
__device__ float g_p [(size_t)NMAX * H];      // W1b.x[n]
__device__ float g_agg[(size_t)NMAX * T * 5 * FIN];
__device__ float g_y[(size_t)NMAX * H];

// ---------------- scalars ----------------
__global__ void k_scalars(const int* __restrict__ mol_deg,
                          const float* __restrict__ bond_emb,
                          const float* __restrict__ enc_w,
                          const float* __restrict__ enc_b) {
    __shared__ float s_num[256], s_den[256];
    int tid = threadIdx.x;
    float num = 0.f, den = 0.f;
    if (tid < 128) {
        float d = (float)mol_deg[tid];
        num = logf((float)tid + 1.0f) * d;
        den = d;
    }
    s_num[tid] = num; s_den[tid] = den;
    __syncthreads();
    for (int off = 128; off > 0; off >>= 1) {
        if (tid < off) { s_num[tid] += s_num[tid + off]; s_den[tid] += s_den[tid + off]; }
        __syncthreads();
    }
    if (tid == 0) g_avg_log = s_num[0] / s_den[0];

    if (tid < 5 * FIN) {
        int b = tid >> 5, g = tid & 31;
        float a = enc_b[g];
        for (int k = 0; k < H; k++) a += bond_emb[b * H + k] * enc_w[k * FIN + g];
        g_enc[b * FIN + g] = a;
    }
}

__global__ void k_zero(int n) {
    int i = blockIdx.x * blockDim.x + threadIdx.x;
    if (i < n) g_deg[i] = 0;
}

__global__ void k_hist(const int* __restrict__ dst, int E) {
    int e = blockIdx.x * blockDim.x + threadIdx.x;
    if (e < E) atomicAdd(&g_deg[dst[e]], 1);
}

// ---------------- parallel 3-phase scan ----------------
__global__ void k_scan1(int n) {
    __shared__ int sh[1024];
    int tid = threadIdx.x;
    int i = blockIdx.x * 1024 + tid;
    int v = (i < n) ? g_deg[i] : 0;
    sh[tid] = v;
    __syncthreads();
    for (int off = 1; off < 1024; off <<= 1) {
        int tv = (tid >= off) ? sh[tid - off] : 0;
        __syncthreads();
        sh[tid] += tv;
        __syncthreads();
    }
    if (i < n) g_off[i] = sh[tid] - v;
    if (tid == 1023) g_part[blockIdx.x] = sh[1023];
}

__global__ void k_scan2(int nb, int n, int E) {
    int l = threadIdx.x;
    int v = (l < nb) ? g_part[l] : 0;
    int s = v;
#pragma unroll
    for (int off = 1; off < 32; off <<= 1) {
        int t = __shfl_up_sync(FULLM, s, off);
        if (l >= off) s += t;
    }
    g_poff[l] = s - v;
    if (l == 0) g_off[n] = E;
}

__global__ void k_scan3(int n) {
    int i = blockIdx.x * 1024 + threadIdx.x;
    if (i < n) {
        int v = g_off[i] + g_poff[blockIdx.x];
        g_off[i] = v;
        g_fill[i] = v;
    }
}

__global__ void k_scatter(const int* __restrict__ dst, const int* __restrict__ src,
                          const int* __restrict__ bond, int E) {
    int e = blockIdx.x * blockDim.x + threadIdx.x;
    if (e < E) {
        int p = atomicAdd(&g_fill[dst[e]], 1);
        g_csr[p] = src[e] | (bond[e] << 27);
    }
}

// ---------------- per-node precompute ----------------
__global__ void __launch_bounds__(128) k_pre(
    const float* __restrict__ atom_x,
    const float* __restrict__ pre_w1, const float* __restrict__ pre_b1, int N) {
    const int l = threadIdx.x & 31;
    const int t = threadIdx.x >> 5;
    float w1a[FIN], w1b[FIN];
#pragma unroll
    for (int f = 0; f < FIN; f++) w1a[f] = pre_w1[(t * 96 + f) * FIN + l];
#pragma unroll
    for (int f = 0; f < FIN; f++) w1b[f] = pre_w1[(t * 96 + 32 + f) * FIN + l];
    const float b1 = pre_b1[t * FIN + l];

    for (int n = blockIdx.x; n < N; n += gridDim.x) {
        float x = atom_x[n * H + t * FIN + l];
        float a0 = b1, p = 0.f;
#pragma unroll
        for (int f = 0; f < FIN; f++) {
            float xf = __shfl_sync(FULLM, x, f);
            a0 += xf * w1a[f];
            p  += xf * w1b[f];
        }
        g_a0[n * H + t * FIN + l] = a0;
        g_p [n * H + t * FIN + l] = p;
    }
}

// ---------------- edge loop: layer2 + multi-aggregation (pairwise f32x2) ----------------
__global__ void __launch_bounds__(128) k_agg(
    const float* __restrict__ pre_w1,
    const float* __restrict__ pre_w2, const float* __restrict__ pre_b2, int N) {
    const int l = threadIdx.x & 31;
    const int t = threadIdx.x >> 5;
    __shared__ __align__(16) float2 rs[4][2][32];   // [warp][buf][feature]

    unsigned long long w2d[FIN];
#pragma unroll
    for (int f = 0; f < FIN; f++) {
        float w = pre_w2[(t * FIN + f) * FIN + l];
        w2d[f] = packf2(w, w);
    }
    const float b2 = pre_b2[t * FIN + l];
    const unsigned long long b2d = packf2(b2, b2);

    float evc0, evc1, evc2, evc3, evc4;
    {
        float w1c[FIN];
#pragma unroll
        for (int f = 0; f < FIN; f++) w1c[f] = pre_w1[(t * 96 + 64 + f) * FIN + l];
        float ev[5];
#pragma unroll
        for (int b = 0; b < 5; b++) {
            float et = g_enc[b * FIN + l];
            float a = 0.f;
#pragma unroll
            for (int f = 0; f < FIN; f++) a += __shfl_sync(FULLM, et, f) * w1c[f];
            ev[b] = a;
        }
        evc0 = ev[0]; evc1 = ev[1]; evc2 = ev[2]; evc3 = ev[3]; evc4 = ev[4];
    }
    const int off = t * FIN + l;

    for (int n = blockIdx.x; n < N; n += gridDim.x) {
        float a0 = g_a0[n * H + off];
        int e0 = g_off[n], e1 = g_off[n + 1];
        int cnt = e1 - e0;
        int npair = cnt >> 1;

        unsigned long long ssum2 = 0ull, ssq2 = 0ull;
        float s_min = FLT_MAX, s_max = -FLT_MAX;
        float tl_sum = 0.f, tl_sq = 0.f;
        int bufsel = 0;

        // prefetch first pair
        float pa = 0.f, pb = 0.f; int ba = 0, bb = 0;
        if (npair > 0) {
            int k0 = g_csr[e0], k1 = g_csr[e0 + 1];
            ba = k0 >> 27; bb = k1 >> 27;
            pa = g_p[(k0 & 0x07ffffff) * H + off];
            pb = g_p[(k1 & 0x07ffffff) * H + off];
        }
        for (int pp = 0; pp < npair; pp++) {
            float cpa = pa, cpb = pb; int cba = ba, cbb = bb;
            if (pp + 1 < npair) {
                int i = e0 + 2 * (pp + 1);
                int k0 = g_csr[i], k1 = g_csr[i + 1];
                ba = k0 >> 27; bb = k1 >> 27;
                pa = g_p[(k0 & 0x07ffffff) * H + off];
                pb = g_p[(k1 & 0x07ffffff) * H + off];
            }
            float ev0 = evc0;
            ev0 = (cba == 1) ? evc1 : ev0;
            ev0 = (cba == 2) ? evc2 : ev0;
            ev0 = (cba == 3) ? evc3 : ev0;
            ev0 = (cba == 4) ? evc4 : ev0;
            float ev1 = evc0;
            ev1 = (cbb == 1) ? evc1 : ev1;
            ev1 = (cbb == 2) ? evc2 : ev1;
            ev1 = (cbb == 3) ? evc3 : ev1;
            ev1 = (cbb == 4) ? evc4 : ev1;
            float r0 = fmaxf(a0 + ev0 + cpa, 0.f);
            float r1 = fmaxf(a0 + ev1 + cpb, 0.f);
            rs[t][bufsel][l] = make_float2(r0, r1);
            __syncwarp();
            unsigned long long ma = b2d, mb = 0ull;
#pragma unroll
            for (int f2 = 0; f2 < 16; f2++) {
                ulonglong2 v = *(const ulonglong2*)&rs[t][bufsel][2 * f2];
                ma = fma2(v.x, w2d[2 * f2], ma);
                mb = fma2(v.y, w2d[2 * f2 + 1], mb);
            }
            unsigned long long mm = add2(ma, mb);
            ssum2 = add2(ssum2, mm);
            ssq2 = fma2(mm, mm, ssq2);
            float m0, m1; unpackf2(mm, m0, m1);
            s_min = fminf(s_min, fminf(m0, m1));
            s_max = fmaxf(s_max, fmaxf(m0, m1));
            bufsel ^= 1;
        }
        if (cnt & 1) {
            int k = g_csr[e1 - 1];
            int cb = k >> 27;
            float p = g_p[(k & 0x07ffffff) * H + off];
            float ev = evc0;
            ev = (cb == 1) ? evc1 : ev;
            ev = (cb == 2) ? evc2 : ev;
            ev = (cb == 3) ? evc3 : ev;
            ev = (cb == 4) ? evc4 : ev;
            float r0 = fmaxf(a0 + ev + p, 0.f);
            rs[t][bufsel][l] = make_float2(r0, 0.f);
            __syncwarp();
            unsigned long long ma = b2d, mb = 0ull;
#pragma unroll
            for (int f2 = 0; f2 < 16; f2++) {
                ulonglong2 v = *(const ulonglong2*)&rs[t][bufsel][2 * f2];
                ma = fma2(v.x, w2d[2 * f2], ma);
                mb = fma2(v.y, w2d[2 * f2 + 1], mb);
            }
            unsigned long long mm = add2(ma, mb);
            float m0, m1; unpackf2(mm, m0, m1);
            tl_sum = m0; tl_sq = m0 * m0;
            s_min = fminf(s_min, m0);
            s_max = fmaxf(s_max, m0);
        }
        float slo, shi, qlo, qhi;
        unpackf2(ssum2, slo, shi);
        unpackf2(ssq2, qlo, qhi);
        float s_sum = slo + shi + tl_sum;
        float s_sq = qlo + qhi + tl_sq;

        float c1 = fmaxf((float)cnt, 1.f);
        float mean = s_sum / c1;
        float mean2 = s_sq / c1;
        float stdv = sqrtf(fmaxf(mean2 - mean * mean, 0.f) + 1e-5f);
        if (cnt == 0) { s_min = 0.f; s_max = 0.f; }
        float* o = g_agg + (size_t)(n * T + t) * 5 * FIN + l;
        o[0 * FIN] = s_sum;
        o[1 * FIN] = mean;
        o[2 * FIN] = s_min;
        o[3 * FIN] = s_max;
        o[4 * FIN] = stdv;
    }
}

// ---------------- post-MLP per tower: 8-node f32x2 blocking ----------------
// dynamic smem: float2 st2[4 warps][4 pairs][512]
extern __shared__ float2 st2d[];
#define ST2(w, pp, f) st2d[(((w) * 4 + (pp)) * 512) + (f)]

__global__ void __launch_bounds__(128) k_post(
    const float* __restrict__ atom_x,
    const float* __restrict__ post_w1, const float* __restrict__ post_b1,
    const float* __restrict__ post_w2, const float* __restrict__ post_b2,
    int N) {
    const int t = blockIdx.y;
    const int w = threadIdx.x >> 5;
    const int g = threadIdx.x & 31;

    const float avg = g_avg_log;
    const float* w1 = post_w1 + (size_t)t * 512 * FIN;
    const float b1 = post_b1[t * FIN + g];
    const float b2v = post_b2[t * FIN + g];
    float w2v[FIN];
#pragma unroll
    for (int f = 0; f < FIN; f++) w2v[f] = post_w2[(t * FIN + f) * FIN + g];
    const int base = blockIdx.x * 64 + w * 16;

    for (int grp = 0; grp < 2; grp++) {
        int n0 = base + grp * 8;
        // stage 8 nodes; node j -> pair (j&3), half (j>>2)
#pragma unroll
        for (int j = 0; j < 8; j++) {
            int n = min(n0 + j, N - 1);
            int cnt = g_deg[n];
            float c1 = fmaxf((float)cnt, 1.f);
            float logd = logf(c1 + 1.f);
            float s1 = logd / avg, s2 = avg / logd;
            float* dstp = ((float*)&ST2(w, j & 3, 0)) + (j >> 2);
            dstp[2 * g] = atom_x[n * H + t * FIN + g];
            const float* ag = g_agg + (size_t)(n * T + t) * 5 * FIN;
#pragma unroll
            for (int a = 0; a < 5; a++) {
                float v = ag[a * FIN + g];
                dstp[2 * (32 + a * FIN + g)] = v;
                dstp[2 * (192 + a * FIN + g)] = v * s1;
                dstp[2 * (352 + a * FIN + g)] = v * s2;
            }
        }
        __syncwarp();
        unsigned long long acc0 = packf2(b1, b1);
        unsigned long long acc1 = acc0, acc2 = acc0, acc3 = acc0;
#pragma unroll 8
        for (int f2 = 0; f2 < 256; f2++) {
            int f = 2 * f2;
            ulonglong2 v0 = *(const ulonglong2*)&ST2(w, 0, f);
            ulonglong2 v1 = *(const ulonglong2*)&ST2(w, 1, f);
            ulonglong2 v2 = *(const ulonglong2*)&ST2(w, 2, f);
            ulonglong2 v3 = *(const ulonglong2*)&ST2(w, 3, f);
            float wv0 = w1[f * FIN + g];
            float wv1 = w1[(f + 1) * FIN + g];
            unsigned long long wd0 = packf2(wv0, wv0);
            unsigned long long wd1 = packf2(wv1, wv1);
            acc0 = fma2(v0.x, wd0, acc0); acc0 = fma2(v0.y, wd1, acc0);
            acc1 = fma2(v1.x, wd0, acc1); acc1 = fma2(v1.y, wd1, acc1);
            acc2 = fma2(v2.x, wd0, acc2); acc2 = fma2(v2.y, wd1, acc2);
            acc3 = fma2(v3.x, wd0, acc3); acc3 = fma2(v3.y, wd1, acc3);
        }
        float m0, m1, m2, m3, m4, m5, m6, m7;
        unpackf2(acc0, m0, m4); unpackf2(acc1, m1, m5);
        unpackf2(acc2, m2, m6); unpackf2(acc3, m3, m7);
        m0 = fmaxf(m0, 0.f); m1 = fmaxf(m1, 0.f); m2 = fmaxf(m2, 0.f); m3 = fmaxf(m3, 0.f);
        m4 = fmaxf(m4, 0.f); m5 = fmaxf(m5, 0.f); m6 = fmaxf(m6, 0.f); m7 = fmaxf(m7, 0.f);
        float o0 = b2v, o1 = b2v, o2 = b2v, o3 = b2v;
        float o4 = b2v, o5 = b2v, o6 = b2v, o7 = b2v;
#pragma unroll
        for (int f = 0; f < FIN; f++) {
            float wv = w2v[f];
            o0 += __shfl_sync(FULLM, m0, f) * wv;
            o1 += __shfl_sync(FULLM, m1, f) * wv;
            o2 += __shfl_sync(FULLM, m2, f) * wv;
            o3 += __shfl_sync(FULLM, m3, f) * wv;
            o4 += __shfl_sync(FULLM, m4, f) * wv;
            o5 += __shfl_sync(FULLM, m5, f) * wv;
            o6 += __shfl_sync(FULLM, m6, f) * wv;
            o7 += __shfl_sync(FULLM, m7, f) * wv;
        }
        float oo[8] = {o0, o1, o2, o3, o4, o5, o6, o7};
#pragma unroll
        for (int j = 0; j < 8; j++) {
            int n = n0 + j;
            if (n < N) g_y[n * H + t * FIN + g] = oo[j];
        }
        __syncwarp();
    }
}

// ---------------- final linear + LayerNorm + ReLU residual ----------------
__global__ void __launch_bounds__(128) k_final(
    const float* __restrict__ atom_x,
    const float* __restrict__ lin_w, const float* __restrict__ lin_b,
    const float* __restrict__ ln_g, const float* __restrict__ ln_b,
    float* __restrict__ out, int N) {
    const int o = threadIdx.x;
    const int wid = o >> 5, l = o & 31;
    __shared__ __align__(16) float sy[4][H];
    __shared__ float red_s[4][4], red_q[4][4];
    const float lb = lin_b[o], gamma = ln_g[o], beta = ln_b[o];

    for (int grp = 0; grp < 4; grp++) {
        int n0 = blockIdx.x * 16 + grp * 4;
        __syncthreads();
#pragma unroll
        for (int j = 0; j < 4; j++) {
            int n = min(n0 + j, N - 1);
            sy[j][o] = g_y[n * H + o];
        }
        __syncthreads();
        const float4* y0 = (const float4*)sy[0];
        const float4* y1 = (const float4*)sy[1];
        const float4* y2 = (const float4*)sy[2];
        const float4* y3 = (const float4*)sy[3];
        float a0 = lb, a1 = lb, a2 = lb, a3 = lb;
#pragma unroll 4
        for (int kk = 0; kk < 32; kk++) {
            float4 v0 = y0[kk], v1 = y1[kk], v2 = y2[kk], v3 = y3[kk];
#pragma unroll
            for (int c = 0; c < 4; c++) {
                float wv = lin_w[(4 * kk + c) * H + o];
                a0 += ((const float*)&v0)[c] * wv;
                a1 += ((const float*)&v1)[c] * wv;
                a2 += ((const float*)&v2)[c] * wv;
                a3 += ((const float*)&v3)[c] * wv;
            }
        }
        float acc[4] = {a0, a1, a2, a3};
#pragma unroll
        for (int j = 0; j < 4; j++) {
            float s = acc[j], q = acc[j] * acc[j];
#pragma unroll
            for (int off = 16; off > 0; off >>= 1) {
                s += __shfl_xor_sync(FULLM, s, off);
                q += __shfl_xor_sync(FULLM, q, off);
            }
            if (l == 0) { red_s[j][wid] = s; red_q[j][wid] = q; }
        }
        __syncthreads();
#pragma unroll
        for (int j = 0; j < 4; j++) {
            int n = n0 + j;
            if (n >= N) continue;
            float s = red_s[j][0] + red_s[j][1] + red_s[j][2] + red_s[j][3];
            float q = red_q[j][0] + red_q[j][1] + red_q[j][2] + red_q[j][3];
            float mu = s * (1.f / 128.f);
            float var = q * (1.f / 128.f) - mu * mu;
            float v = (acc[j] - mu) * rsqrtf(var + 1e-5f) * gamma + beta;
            out[n * H + o] = atom_x[n * H + o] + fmaxf(v, 0.f);
        }
    }
}

// ---------------- launch ----------------
extern "C" void kernel_launch(void* const* d_in, const int* in_sizes, int n_in,
                              void* d_out, int out_size) {
    const float* atom_x  = (const float*)d_in[0];
    const int*   bond_x  = (const int*)d_in[1];
    const int*   edge_ix = (const int*)d_in[2];
    const int*   mol_deg = (const int*)d_in[3];
    const float* bond_emb = (const float*)d_in[4];
    const float* enc_w   = (const float*)d_in[5];
    const float* enc_b   = (const float*)d_in[6];
    const float* pre_w1  = (const float*)d_in[7];
    const float* pre_b1  = (const float*)d_in[8];
    const float* pre_w2  = (const float*)d_in[9];
    const float* pre_b2  = (const float*)d_in[10];
    const float* post_w1 = (const float*)d_in[11];
    const float* post_b1 = (const float*)d_in[12];
    const float* post_w2 = (const float*)d_in[13];
    const float* post_b2 = (const float*)d_in[14];
    const float* lin_w   = (const float*)d_in[15];
    const float* lin_b   = (const float*)d_in[16];
    const float* ln_g    = (const float*)d_in[17];
    const float* ln_b    = (const float*)d_in[18];
    float* out = (float*)d_out;

    int N = in_sizes[0] / H;
    int E = in_sizes[1];
    const int* src = edge_ix;
    const int* dst = edge_ix + E;
    int nb = (N + 1023) / 1024;

    static int smem_set = 0;
    if (!smem_set) {
        cudaFuncSetAttribute(k_post, cudaFuncAttributeMaxDynamicSharedMemorySize, 65536);
        smem_set = 1;
    }

    k_zero<<<(N + 511) / 512, 512>>>(N);
    k_scalars<<<1, 256>>>(mol_deg, bond_emb, enc_w, enc_b);
    k_hist<<<(E + 255) / 256, 256>>>(dst, E);
    k_scan1<<<nb, 1024>>>(N);
    k_scan2<<<1, 32>>>(nb, N, E);
    k_scan3<<<nb, 1024>>>(N);
    k_scatter<<<(E + 255) / 256, 256>>>(dst, src, bond_x, E);
    k_pre<<<592, 128>>>(atom_x, pre_w1, pre_b1, N);
    k_agg<<<1184, 128>>>(pre_w1, pre_w2, pre_b2, N);
    k_post<<<dim3((N + 63) / 64, T), 128, 65536>>>(atom_x, post_w1, post_b1, post_w2, post_b2, N);
    k_final<<<(N + 15) / 16, 128>>>(atom_x, lin_w, lin_b, ln_g, ln_b, out, N);
}

// round 4
// speedup vs baseline: 2.1694x; 1.0365x over previous
#include <cuda_runtime.h>
#include <math.h>
#include <float.h>

#define NMAX 20000
#define EMAX 320000
#define H 128
#define T 4
#define FIN 32
#define FULLM 0xffffffffu
#define NB 132   // resident blocks for fused setup (must be <= SM count)

typedef unsigned long long ull;

// ---------------- f32x2 packed helpers ----------------
__device__ __forceinline__ ull packf2(float lo, float hi) {
    ull r;
    asm("mov.b64 %0, {%1, %2};" : "=l"(r) : "r"(__float_as_uint(lo)), "r"(__float_as_uint(hi)));
    return r;
}
__device__ __forceinline__ void unpackf2(ull v, float& lo, float& hi) {
    unsigned int a, b;
    asm("mov.b64 {%0, %1}, %2;" : "=r"(a), "=r"(b) : "l"(v));
    lo = __uint_as_float(a); hi = __uint_as_float(b);
}
__device__ __forceinline__ ull fma2(ull a, ull b, ull c) {
    ull d;
    asm("fma.rn.f32x2 %0, %1, %2, %3;" : "=l"(d) : "l"(a), "l"(b), "l"(c));
    return d;
}
__device__ __forceinline__ ull add2(ull a, ull b) {
    ull d;
    asm("add.rn.f32x2 %0, %1, %2;" : "=l"(d) : "l"(a), "l"(b));
    return d;
}

// ---------------- device scratch ----------------
__device__ float g_avg_log;
__device__ float g_enc[5 * FIN];
__device__ int   g_deg[NMAX];
__device__ int   g_off[NMAX + 1];
__device__ int   g_fill[NMAX];
__device__ int   g_csr[EMAX];                 // packed: src | (bond<<27)
__device__ int   g_part[NB];
__device__ int   g_poff[NB];
__device__ float g_a0[(size_t)NMAX * H];
__device__ float g_p [(size_t)NMAX * H];
__device__ float g_agg[(size_t)NMAX * T * 5 * FIN];
__device__ float g_y[(size_t)NMAX * H];
__device__ unsigned int g_bar;                // zero-init at load; reset at end of setup
__device__ unsigned int g_done;

// ---------------- fused setup: zero + hist + scan + scatter ----------------
__device__ __forceinline__ void grid_bar(unsigned target) {
    __syncthreads();
    if (threadIdx.x == 0) {
        __threadfence();
        atomicAdd(&g_bar, 1u);
        while (*((volatile unsigned int*)&g_bar) < target) { }
        __threadfence();
    }
    __syncthreads();
}

__global__ void __launch_bounds__(256) k_setup(
    const int* __restrict__ dst, const int* __restrict__ src,
    const int* __restrict__ bond, int N, int E) {
    const int tid = threadIdx.x, b = blockIdx.x;
    const int gsz = NB * 256;
    const int gid = b * 256 + tid;
    __shared__ int sh[256];

    // P0: zero degree counters
    for (int i = gid; i < N; i += gsz) __stcg(&g_deg[i], 0);
    grid_bar(NB * 1);

    // P1: degree histogram
    for (int e = gid; e < E; e += gsz) atomicAdd(&g_deg[__ldg(&dst[e])], 1);
    grid_bar(NB * 2);

    // P2: per-block chunk scan (chunk <= 256)
    const int chunk = (N + NB - 1) / NB;
    const int i = b * chunk + tid;
    int v = (tid < chunk && i < N) ? __ldcg(&g_deg[i]) : 0;
    sh[tid] = v;
    __syncthreads();
    for (int off = 1; off < 256; off <<= 1) {
        int tv = (tid >= off) ? sh[tid - off] : 0;
        __syncthreads();
        sh[tid] += tv;
        __syncthreads();
    }
    int local_excl = sh[tid] - v;
    if (tid == 255) __stcg(&g_part[b], sh[255]);
    grid_bar(NB * 3);

    // P3: block 0 scans block totals
    if (b == 0) {
        int v2 = (tid < NB) ? __ldcg(&g_part[tid]) : 0;
        sh[tid] = v2;
        __syncthreads();
        for (int off = 1; off < 256; off <<= 1) {
            int tv = (tid >= off) ? sh[tid - off] : 0;
            __syncthreads();
            sh[tid] += tv;
            __syncthreads();
        }
        if (tid < NB) __stcg(&g_poff[tid], sh[tid] - v2);
        if (tid == 0) __stcg(&g_off[N], E);
    }
    grid_bar(NB * 4);

    // P4: finalize offsets
    {
        int po = __ldcg(&g_poff[b]);
        if (tid < chunk && i < N) {
            int vv = local_excl + po;
            __stcg(&g_off[i], vv);
            __stcg(&g_fill[i], vv);
        }
    }
    grid_bar(NB * 5);

    // P5: scatter edges into CSR
    for (int e = gid; e < E; e += gsz) {
        int d = __ldg(&dst[e]);
        int p = atomicAdd(&g_fill[d], 1);
        __stcg(&g_csr[p], __ldg(&src[e]) | (__ldg(&bond[e]) << 27));
    }

    // reset barrier state for next graph replay (last block out)
    __syncthreads();
    if (tid == 0) {
        if (atomicAdd(&g_done, 1u) == NB - 1) {
            atomicExch(&g_bar, 0u);
            atomicExch(&g_done, 0u);
        }
    }
}

// ---------------- scalars: avg_log + bond encode table ----------------
__global__ void k_scalars(const int* __restrict__ mol_deg,
                          const float* __restrict__ bond_emb,
                          const float* __restrict__ enc_w,
                          const float* __restrict__ enc_b) {
    __shared__ float s_num[256], s_den[256];
    int tid = threadIdx.x;
    float num = 0.f, den = 0.f;
    if (tid < 128) {
        float d = (float)mol_deg[tid];
        num = logf((float)tid + 1.0f) * d;
        den = d;
    }
    s_num[tid] = num; s_den[tid] = den;
    __syncthreads();
    for (int off = 128; off > 0; off >>= 1) {
        if (tid < off) { s_num[tid] += s_num[tid + off]; s_den[tid] += s_den[tid + off]; }
        __syncthreads();
    }
    if (tid == 0) g_avg_log = s_num[0] / s_den[0];

    if (tid < 5 * FIN) {
        int b = tid >> 5, g = tid & 31;
        float a = enc_b[g];
        for (int k = 0; k < H; k++) a += bond_emb[b * H + k] * enc_w[k * FIN + g];
        g_enc[b * FIN + g] = a;
    }
}

// ---------------- per-node precompute: A0 = b1 + W1a.x, P = W1b.x ----------------
__global__ void __launch_bounds__(128) k_pre(
    const float* __restrict__ atom_x,
    const float* __restrict__ pre_w1, const float* __restrict__ pre_b1, int N) {
    const int l = threadIdx.x & 31;
    const int t = threadIdx.x >> 5;
    float w1a[FIN], w1b[FIN];
#pragma unroll
    for (int f = 0; f < FIN; f++) w1a[f] = pre_w1[(t * 96 + f) * FIN + l];
#pragma unroll
    for (int f = 0; f < FIN; f++) w1b[f] = pre_w1[(t * 96 + 32 + f) * FIN + l];
    const float b1 = pre_b1[t * FIN + l];

    for (int n = blockIdx.x; n < N; n += gridDim.x) {
        float x = atom_x[n * H + t * FIN + l];
        float a0 = b1, p = 0.f;
#pragma unroll
        for (int f = 0; f < FIN; f++) {
            float xf = __shfl_sync(FULLM, x, f);
            a0 += xf * w1a[f];
            p  += xf * w1b[f];
        }
        g_a0[n * H + t * FIN + l] = a0;
        g_p [n * H + t * FIN + l] = p;
    }
}

// ---------------- edge loop: dual-node interleaved, pairwise f32x2 ----------------
__device__ __forceinline__ ull dot32(const float2* buf, const ull* w2d, ull seed) {
    ull ma = seed, mb = 0ull;
#pragma unroll
    for (int f2 = 0; f2 < 16; f2++) {
        ulonglong2 v = *(const ulonglong2*)&buf[2 * f2];
        ma = fma2(v.x, w2d[2 * f2], ma);
        mb = fma2(v.y, w2d[2 * f2 + 1], mb);
    }
    return add2(ma, mb);
}

__global__ void __launch_bounds__(128) k_agg(
    const float* __restrict__ pre_w1,
    const float* __restrict__ pre_w2, const float* __restrict__ pre_b2, int N) {
    const int l = threadIdx.x & 31;
    const int t = threadIdx.x >> 5;
    __shared__ __align__(16) float2 rs[4][2][2][32];   // [warp][parity][slot][lane]

    ull w2d[FIN];
#pragma unroll
    for (int f = 0; f < FIN; f++) {
        float w = pre_w2[(t * FIN + f) * FIN + l];
        w2d[f] = packf2(w, w);
    }
    const float b2 = pre_b2[t * FIN + l];
    const ull b2d = packf2(b2, b2);

    float evc0, evc1, evc2, evc3, evc4;
    {
        float w1c[FIN];
#pragma unroll
        for (int f = 0; f < FIN; f++) w1c[f] = pre_w1[(t * 96 + 64 + f) * FIN + l];
        float ev[5];
#pragma unroll
        for (int b = 0; b < 5; b++) {
            float et = g_enc[b * FIN + l];
            float a = 0.f;
#pragma unroll
            for (int f = 0; f < FIN; f++) a += __shfl_sync(FULLM, et, f) * w1c[f];
            ev[b] = a;
        }
        evc0 = ev[0]; evc1 = ev[1]; evc2 = ev[2]; evc3 = ev[3]; evc4 = ev[4];
    }
    const int off = t * FIN + l;
    const int half = (N + 1) >> 1;

#define EVSEL(bb) ({ float _e = evc0; _e = ((bb)==1)?evc1:_e; _e = ((bb)==2)?evc2:_e; \
                     _e = ((bb)==3)?evc3:_e; _e = ((bb)==4)?evc4:_e; _e; })

    for (int n = blockIdx.x; n < half; n += gridDim.x) {
        const int nA = n, nB = n + half;
        const bool hasB = nB < N;
        float a0A = g_a0[nA * H + off];
        int e0A = g_off[nA], e1A = g_off[nA + 1];
        float a0B = 0.f; int e0B = 0, e1B = 0;
        if (hasB) { a0B = g_a0[nB * H + off]; e0B = g_off[nB]; e1B = g_off[nB + 1]; }
        const int cntA = e1A - e0A, cntB = e1B - e0B;
        const int pAcnt = cntA >> 1, pBcnt = cntB >> 1;
        const int np = max(pAcnt, pBcnt);

        ull sA = 0ull, qA = 0ull, sB = 0ull, qB = 0ull;
        float minA = FLT_MAX, maxA = -FLT_MAX, minB = FLT_MAX, maxB = -FLT_MAX;
        float tsA = 0.f, tqA = 0.f, tsB = 0.f, tqB = 0.f;

        // prefetch pair 0 of each stream
        float paA = 0.f, pbA = 0.f, paB = 0.f, pbB = 0.f;
        int baA = 0, bbA = 0, baB = 0, bbB = 0;
        if (pAcnt > 0) {
            int k0 = g_csr[e0A], k1 = g_csr[e0A + 1];
            baA = k0 >> 27; bbA = k1 >> 27;
            paA = g_p[(k0 & 0x07ffffff) * H + off];
            pbA = g_p[(k1 & 0x07ffffff) * H + off];
        }
        if (pBcnt > 0) {
            int k0 = g_csr[e0B], k1 = g_csr[e0B + 1];
            baB = k0 >> 27; bbB = k1 >> 27;
            paB = g_p[(k0 & 0x07ffffff) * H + off];
            pbB = g_p[(k1 & 0x07ffffff) * H + off];
        }

        for (int i = 0; i < np; i++) {
            const int par = i & 1;
            const bool dA = i < pAcnt, dB = i < pBcnt;
            if (dA) {
                float r0 = fmaxf(a0A + EVSEL(baA) + paA, 0.f);
                float r1 = fmaxf(a0A + EVSEL(bbA) + pbA, 0.f);
                rs[t][par][0][l] = make_float2(r0, r1);
            }
            if (dB) {
                float r0 = fmaxf(a0B + EVSEL(baB) + paB, 0.f);
                float r1 = fmaxf(a0B + EVSEL(bbB) + pbB, 0.f);
                rs[t][par][1][l] = make_float2(r0, r1);
            }
            // prefetch next pairs (4 independent gathers in flight)
            if (i + 1 < pAcnt) {
                int idx = e0A + 2 * (i + 1);
                int k0 = g_csr[idx], k1 = g_csr[idx + 1];
                baA = k0 >> 27; bbA = k1 >> 27;
                paA = g_p[(k0 & 0x07ffffff) * H + off];
                pbA = g_p[(k1 & 0x07ffffff) * H + off];
            }
            if (i + 1 < pBcnt) {
                int idx = e0B + 2 * (i + 1);
                int k0 = g_csr[idx], k1 = g_csr[idx + 1];
                baB = k0 >> 27; bbB = k1 >> 27;
                paB = g_p[(k0 & 0x07ffffff) * H + off];
                pbB = g_p[(k1 & 0x07ffffff) * H + off];
            }
            __syncwarp();
            if (dA) {
                ull mm = dot32(rs[t][par][0], w2d, b2d);
                sA = add2(sA, mm);
                qA = fma2(mm, mm, qA);
                float m0, m1; unpackf2(mm, m0, m1);
                minA = fminf(minA, fminf(m0, m1));
                maxA = fmaxf(maxA, fmaxf(m0, m1));
            }
            if (dB) {
                ull mm = dot32(rs[t][par][1], w2d, b2d);
                sB = add2(sB, mm);
                qB = fma2(mm, mm, qB);
                float m0, m1; unpackf2(mm, m0, m1);
                minB = fminf(minB, fminf(m0, m1));
                maxB = fmaxf(maxB, fmaxf(m0, m1));
            }
        }

        // odd tails
        const bool tA = (cntA & 1) != 0, tB = (cntB & 1) != 0;
        if (tA | tB) {
            const int par = np & 1;
            if (tA) {
                int k = g_csr[e1A - 1];
                int cb = k >> 27;
                float p = g_p[(k & 0x07ffffff) * H + off];
                float r0 = fmaxf(a0A + EVSEL(cb) + p, 0.f);
                rs[t][par][0][l] = make_float2(r0, 0.f);
            }
            if (tB) {
                int k = g_csr[e1B - 1];
                int cb = k >> 27;
                float p = g_p[(k & 0x07ffffff) * H + off];
                float r0 = fmaxf(a0B + EVSEL(cb) + p, 0.f);
                rs[t][par][1][l] = make_float2(r0, 0.f);
            }
            __syncwarp();
            if (tA) {
                ull mm = dot32(rs[t][par][0], w2d, b2d);
                float m0, m1; unpackf2(mm, m0, m1);
                tsA = m0; tqA = m0 * m0;
                minA = fminf(minA, m0); maxA = fmaxf(maxA, m0);
            }
            if (tB) {
                ull mm = dot32(rs[t][par][1], w2d, b2d);
                float m0, m1; unpackf2(mm, m0, m1);
                tsB = m0; tqB = m0 * m0;
                minB = fminf(minB, m0); maxB = fmaxf(maxB, m0);
            }
        }

        // finalize A
        {
            float slo, shi, qlo, qhi;
            unpackf2(sA, slo, shi); unpackf2(qA, qlo, qhi);
            float s_sum = slo + shi + tsA;
            float s_sq  = qlo + qhi + tqA;
            float c1 = fmaxf((float)cntA, 1.f);
            float mean = s_sum / c1;
            float stdv = sqrtf(fmaxf(s_sq / c1 - mean * mean, 0.f) + 1e-5f);
            float mn = minA, mx = maxA;
            if (cntA == 0) { mn = 0.f; mx = 0.f; }
            float* o = g_agg + (size_t)(nA * T + t) * 5 * FIN + l;
            o[0 * FIN] = s_sum; o[1 * FIN] = mean; o[2 * FIN] = mn;
            o[3 * FIN] = mx;    o[4 * FIN] = stdv;
        }
        if (hasB) {
            float slo, shi, qlo, qhi;
            unpackf2(sB, slo, shi); unpackf2(qB, qlo, qhi);
            float s_sum = slo + shi + tsB;
            float s_sq  = qlo + qhi + tqB;
            float c1 = fmaxf((float)cntB, 1.f);
            float mean = s_sum / c1;
            float stdv = sqrtf(fmaxf(s_sq / c1 - mean * mean, 0.f) + 1e-5f);
            float mn = minB, mx = maxB;
            if (cntB == 0) { mn = 0.f; mx = 0.f; }
            float* o = g_agg + (size_t)(nB * T + t) * 5 * FIN + l;
            o[0 * FIN] = s_sum; o[1 * FIN] = mean; o[2 * FIN] = mn;
            o[3 * FIN] = mx;    o[4 * FIN] = stdv;
        }
    }
#undef EVSEL
}

// ---------------- post-MLP per tower: 8-node f32x2 blocking ----------------
extern __shared__ float2 st2d[];
#define ST2(w, pp, f) st2d[(((w) * 4 + (pp)) * 512) + (f)]

__global__ void __launch_bounds__(128) k_post(
    const float* __restrict__ atom_x,
    const float* __restrict__ post_w1, const float* __restrict__ post_b1,
    const float* __restrict__ post_w2, const float* __restrict__ post_b2,
    int N) {
    const int t = blockIdx.y;
    const int w = threadIdx.x >> 5;
    const int g = threadIdx.x & 31;

    const float avg = g_avg_log;
    const float* w1 = post_w1 + (size_t)t * 512 * FIN;
    const float b1 = post_b1[t * FIN + g];
    const float b2v = post_b2[t * FIN + g];
    float w2v[FIN];
#pragma unroll
    for (int f = 0; f < FIN; f++) w2v[f] = post_w2[(t * FIN + f) * FIN + g];
    const int base = blockIdx.x * 64 + w * 16;

    for (int grp = 0; grp < 2; grp++) {
        int n0 = base + grp * 8;
#pragma unroll
        for (int j = 0; j < 8; j++) {
            int n = min(n0 + j, N - 1);
            int cnt = g_deg[n];
            float c1 = fmaxf((float)cnt, 1.f);
            float logd = logf(c1 + 1.f);
            float s1 = logd / avg, s2 = avg / logd;
            float* dstp = ((float*)&ST2(w, j & 3, 0)) + (j >> 2);
            dstp[2 * g] = atom_x[n * H + t * FIN + g];
            const float* ag = g_agg + (size_t)(n * T + t) * 5 * FIN;
#pragma unroll
            for (int a = 0; a < 5; a++) {
                float v = ag[a * FIN + g];
                dstp[2 * (32 + a * FIN + g)] = v;
                dstp[2 * (192 + a * FIN + g)] = v * s1;
                dstp[2 * (352 + a * FIN + g)] = v * s2;
            }
        }
        __syncwarp();
        ull acc0 = packf2(b1, b1);
        ull acc1 = acc0, acc2 = acc0, acc3 = acc0;
#pragma unroll 8
        for (int f2 = 0; f2 < 256; f2++) {
            int f = 2 * f2;
            ulonglong2 v0 = *(const ulonglong2*)&ST2(w, 0, f);
            ulonglong2 v1 = *(const ulonglong2*)&ST2(w, 1, f);
            ulonglong2 v2 = *(const ulonglong2*)&ST2(w, 2, f);
            ulonglong2 v3 = *(const ulonglong2*)&ST2(w, 3, f);
            float wv0 = w1[f * FIN + g];
            float wv1 = w1[(f + 1) * FIN + g];
            ull wd0 = packf2(wv0, wv0);
            ull wd1 = packf2(wv1, wv1);
            acc0 = fma2(v0.x, wd0, acc0); acc0 = fma2(v0.y, wd1, acc0);
            acc1 = fma2(v1.x, wd0, acc1); acc1 = fma2(v1.y, wd1, acc1);
            acc2 = fma2(v2.x, wd0, acc2); acc2 = fma2(v2.y, wd1, acc2);
            acc3 = fma2(v3.x, wd0, acc3); acc3 = fma2(v3.y, wd1, acc3);
        }
        float m0, m1, m2, m3, m4, m5, m6, m7;
        unpackf2(acc0, m0, m4); unpackf2(acc1, m1, m5);
        unpackf2(acc2, m2, m6); unpackf2(acc3, m3, m7);
        m0 = fmaxf(m0, 0.f); m1 = fmaxf(m1, 0.f); m2 = fmaxf(m2, 0.f); m3 = fmaxf(m3, 0.f);
        m4 = fmaxf(m4, 0.f); m5 = fmaxf(m5, 0.f); m6 = fmaxf(m6, 0.f); m7 = fmaxf(m7, 0.f);
        float o0 = b2v, o1 = b2v, o2 = b2v, o3 = b2v;
        float o4 = b2v, o5 = b2v, o6 = b2v, o7 = b2v;
#pragma unroll
        for (int f = 0; f < FIN; f++) {
            float wv = w2v[f];
            o0 += __shfl_sync(FULLM, m0, f) * wv;
            o1 += __shfl_sync(FULLM, m1, f) * wv;
            o2 += __shfl_sync(FULLM, m2, f) * wv;
            o3 += __shfl_sync(FULLM, m3, f) * wv;
            o4 += __shfl_sync(FULLM, m4, f) * wv;
            o5 += __shfl_sync(FULLM, m5, f) * wv;
            o6 += __shfl_sync(FULLM, m6, f) * wv;
            o7 += __shfl_sync(FULLM, m7, f) * wv;
        }
        float oo[8] = {o0, o1, o2, o3, o4, o5, o6, o7};
#pragma unroll
        for (int j = 0; j < 8; j++) {
            int n = n0 + j;
            if (n < N) g_y[n * H + t * FIN + g] = oo[j];
        }
        __syncwarp();
    }
}

// ---------------- final linear + LayerNorm + ReLU residual ----------------
__global__ void __launch_bounds__(128) k_final(
    const float* __restrict__ atom_x,
    const float* __restrict__ lin_w, const float* __restrict__ lin_b,
    const float* __restrict__ ln_g, const float* __restrict__ ln_b,
    float* __restrict__ out, int N) {
    const int o = threadIdx.x;
    const int wid = o >> 5, l = o & 31;
    __shared__ __align__(16) float sy[4][H];
    __shared__ float red_s[4][4], red_q[4][4];
    const float lb = lin_b[o], gamma = ln_g[o], beta = ln_b[o];

    for (int grp = 0; grp < 4; grp++) {
        int n0 = blockIdx.x * 16 + grp * 4;
        __syncthreads();
#pragma unroll
        for (int j = 0; j < 4; j++) {
            int n = min(n0 + j, N - 1);
            sy[j][o] = g_y[n * H + o];
        }
        __syncthreads();
        const float4* y0 = (const float4*)sy[0];
        const float4* y1 = (const float4*)sy[1];
        const float4* y2 = (const float4*)sy[2];
        const float4* y3 = (const float4*)sy[3];
        float a0 = lb, a1 = lb, a2 = lb, a3 = lb;
#pragma unroll 4
        for (int kk = 0; kk < 32; kk++) {
            float4 v0 = y0[kk], v1 = y1[kk], v2 = y2[kk], v3 = y3[kk];
#pragma unroll
            for (int c = 0; c < 4; c++) {
                float wv = lin_w[(4 * kk + c) * H + o];
                a0 += ((const float*)&v0)[c] * wv;
                a1 += ((const float*)&v1)[c] * wv;
                a2 += ((const float*)&v2)[c] * wv;
                a3 += ((const float*)&v3)[c] * wv;
            }
        }
        float acc[4] = {a0, a1, a2, a3};
#pragma unroll
        for (int j = 0; j < 4; j++) {
            float s = acc[j], q = acc[j] * acc[j];
#pragma unroll
            for (int off = 16; off > 0; off >>= 1) {
                s += __shfl_xor_sync(FULLM, s, off);
                q += __shfl_xor_sync(FULLM, q, off);
            }
            if (l == 0) { red_s[j][wid] = s; red_q[j][wid] = q; }
        }
        __syncthreads();
#pragma unroll
        for (int j = 0; j < 4; j++) {
            int n = n0 + j;
            if (n >= N) continue;
            float s = red_s[j][0] + red_s[j][1] + red_s[j][2] + red_s[j][3];
            float q = red_q[j][0] + red_q[j][1] + red_q[j][2] + red_q[j][3];
            float mu = s * (1.f / 128.f);
            float var = q * (1.f / 128.f) - mu * mu;
            float v = (acc[j] - mu) * rsqrtf(var + 1e-5f) * gamma + beta;
            out[n * H + o] = atom_x[n * H + o] + fmaxf(v, 0.f);
        }
    }
}

// ---------------- launch ----------------
extern "C" void kernel_launch(void* const* d_in, const int* in_sizes, int n_in,
                              void* d_out, int out_size) {
    const float* atom_x  = (const float*)d_in[0];
    const int*   bond_x  = (const int*)d_in[1];
    const int*   edge_ix = (const int*)d_in[2];
    const int*   mol_deg = (const int*)d_in[3];
    const float* bond_emb = (const float*)d_in[4];
    const float* enc_w   = (const float*)d_in[5];
    const float* enc_b   = (const float*)d_in[6];
    const float* pre_w1  = (const float*)d_in[7];
    const float* pre_b1  = (const float*)d_in[8];
    const float* pre_w2  = (const float*)d_in[9];
    const float* pre_b2  = (const float*)d_in[10];
    const float* post_w1 = (const float*)d_in[11];
    const float* post_b1 = (const float*)d_in[12];
    const float* post_w2 = (const float*)d_in[13];
    const float* post_b2 = (const float*)d_in[14];
    const float* lin_w   = (const float*)d_in[15];
    const float* lin_b   = (const float*)d_in[16];
    const float* ln_g    = (const float*)d_in[17];
    const float* ln_b    = (const float*)d_in[18];
    float* out = (float*)d_out;

    int N = in_sizes[0] / H;
    int E = in_sizes[1];
    const int* src = edge_ix;
    const int* dst = edge_ix + E;

    static int smem_set = 0;
    if (!smem_set) {
        cudaFuncSetAttribute(k_post, cudaFuncAttributeMaxDynamicSharedMemorySize, 65536);
        smem_set = 1;
    }

    k_setup<<<NB, 256>>>(dst, src, bond_x, N, E);                          // 0
    k_pre<<<592, 128>>>(atom_x, pre_w1, pre_b1, N);                        // 1
    k_scalars<<<1, 256>>>(mol_deg, bond_emb, enc_w, enc_b);                // 2
    k_agg<<<1184, 128>>>(pre_w1, pre_w2, pre_b2, N);                       // 3  <- ncu target
    k_post<<<dim3((N + 63) / 64, T), 128, 65536>>>(atom_x, post_w1, post_b1, post_w2, post_b2, N);
    k_final<<<(N + 15) / 16, 128>>>(atom_x, lin_w, lin_b, ln_g, ln_b, out, N);
}